// round 3
// baseline (speedup 1.0000x reference)
#include <cuda_runtime.h>

#define NN 100000
#define NE 3200000
#define C1 256
#define C2 64
#define C3 128

// Scratch (static device globals — no allocation allowed)
__device__ float g_h1pre[(size_t)NN * C2];
__device__ float g_h1agg[(size_t)NN * C2];
__device__ float g_h2pre[(size_t)NN * C3];
__device__ float g_h2agg[(size_t)NN * C3];
__device__ int   g_deg[NN];
__device__ float g_dinv[NN];
__device__ float g_gsum[C3];

// ---------------- degree / norm ----------------
__global__ void deginit_k() {
    int i = blockIdx.x * blockDim.x + threadIdx.x;
    if (i < NN) g_deg[i] = 1;          // self loop
    if (i < C3) g_gsum[i] = 0.f;
}

__global__ void degcnt_k(const int* __restrict__ ei) {
    int e = blockIdx.x * blockDim.x + threadIdx.x;
    if (e < NE) atomicAdd(&g_deg[ei[NE + e]], 1);
}

__global__ void dinv_k() {
    int i = blockIdx.x * blockDim.x + threadIdx.x;
    if (i < NN) g_dinv[i] = rsqrtf((float)g_deg[i]);
}

// ---------------- GEMM1: h1pre = x @ W1  (no bias yet) ----------------
__global__ void gemm1_k(const float* __restrict__ x, const float* __restrict__ W1) {
    __shared__ float xs[64][68];
    __shared__ float ws[64][68];
    int row0 = blockIdx.x * 64;
    int tid = threadIdx.x;
    int ty = tid >> 4, tx = tid & 15;
    float acc[4][4];
#pragma unroll
    for (int i = 0; i < 4; i++)
#pragma unroll
        for (int j = 0; j < 4; j++) acc[i][j] = 0.f;

    for (int kc = 0; kc < C1; kc += 64) {
#pragma unroll
        for (int i = 0; i < 4; i++) {
            int li = tid + i * 256;            // float4 index 0..1023
            int r = li >> 4, c4 = li & 15;
            int grow = row0 + r;
            float4 v = make_float4(0.f, 0.f, 0.f, 0.f);
            if (grow < NN) v = *(const float4*)(x + (size_t)grow * C1 + kc + c4 * 4);
            *(float4*)&xs[r][c4 * 4] = v;
        }
#pragma unroll
        for (int i = 0; i < 4; i++) {
            int li = tid + i * 256;
            int r = li >> 4, c4 = li & 15;
            *(float4*)&ws[r][c4 * 4] = *(const float4*)(W1 + (size_t)(kc + r) * C2 + c4 * 4);
        }
        __syncthreads();
#pragma unroll
        for (int k = 0; k < 64; k++) {
            float a[4], b[4];
#pragma unroll
            for (int i = 0; i < 4; i++) a[i] = xs[ty * 4 + i][k];
#pragma unroll
            for (int j = 0; j < 4; j++) b[j] = ws[k][tx * 4 + j];
#pragma unroll
            for (int i = 0; i < 4; i++)
#pragma unroll
                for (int j = 0; j < 4; j++) acc[i][j] += a[i] * b[j];
        }
        __syncthreads();
    }
#pragma unroll
    for (int i = 0; i < 4; i++) {
        int grow = row0 + ty * 4 + i;
        if (grow < NN) {
            float4 v = make_float4(acc[i][0], acc[i][1], acc[i][2], acc[i][3]);
            *(float4*)(g_h1pre + (size_t)grow * C2 + tx * 4) = v;
        }
    }
}

// ---------------- self-loop init: agg = dinv[i]^2 * pre ----------------
__global__ void self1_k() {
    int i = blockIdx.x * blockDim.x + threadIdx.x;   // float4 index
    if (i >= NN * 16) return;
    int node = i >> 4;
    float dv = g_dinv[node];
    float nm = dv * dv;
    float4 v = *((const float4*)g_h1pre + i);
    v.x *= nm; v.y *= nm; v.z *= nm; v.w *= nm;
    *((float4*)g_h1agg + i) = v;
}

__global__ void self2_k() {
    int i = blockIdx.x * blockDim.x + threadIdx.x;
    if (i >= NN * 32) return;
    int node = i >> 5;
    float dv = g_dinv[node];
    float nm = dv * dv;
    float4 v = *((const float4*)g_h2pre + i);
    v.x *= nm; v.y *= nm; v.z *= nm; v.w *= nm;
    *((float4*)g_h2agg + i) = v;
}

// ---------------- edge scatter: one warp per edge ----------------
__global__ void agg1_k(const int* __restrict__ ei) {
    int w = (blockIdx.x * blockDim.x + threadIdx.x) >> 5;
    if (w >= NE) return;
    int lane = threadIdx.x & 31;
    int s = __ldg(ei + w);
    int d = __ldg(ei + NE + w);
    float nm = __ldg(g_dinv + s) * __ldg(g_dinv + d);
    float2 v = *(const float2*)(g_h1pre + (size_t)s * C2 + lane * 2);
    v.x *= nm; v.y *= nm;
    atomicAdd((float2*)(g_h1agg + (size_t)d * C2 + lane * 2), v);
}

__global__ void agg2_k(const int* __restrict__ ei) {
    int w = (blockIdx.x * blockDim.x + threadIdx.x) >> 5;
    if (w >= NE) return;
    int lane = threadIdx.x & 31;
    int s = __ldg(ei + w);
    int d = __ldg(ei + NE + w);
    float nm = __ldg(g_dinv + s) * __ldg(g_dinv + d);
    float4 v = *(const float4*)(g_h2pre + (size_t)s * C3 + lane * 4);
    v.x *= nm; v.y *= nm; v.z *= nm; v.w *= nm;
    atomicAdd((float4*)(g_h2agg + (size_t)d * C3 + lane * 4), v);
}

// ---------------- GEMM2: h2pre = relu(h1agg + b1) @ W2 ----------------
__global__ void gemm2_k(const float* __restrict__ W2, const float* __restrict__ b1) {
    __shared__ float xs[64][64];
    __shared__ float ws[64][128];
    int row0 = blockIdx.x * 64;
    int tid = threadIdx.x;
    int ty = tid >> 4, tx = tid & 15;

    // load W2 fully: 64x128 floats = 2048 float4, 8 per thread
#pragma unroll
    for (int i = 0; i < 8; i++) {
        int li = tid + i * 256;            // 32 float4 per row
        int r = li >> 5, c4 = li & 31;
        *(float4*)&ws[r][c4 * 4] = *(const float4*)(W2 + (size_t)r * C3 + c4 * 4);
    }
    // load x tile with bias + relu fused
#pragma unroll
    for (int i = 0; i < 4; i++) {
        int li = tid + i * 256;            // 16 float4 per row
        int r = li >> 4, c4 = li & 15;
        int grow = row0 + r;
        float4 v = make_float4(0.f, 0.f, 0.f, 0.f);
        if (grow < NN) {
            v = *(const float4*)(g_h1agg + (size_t)grow * C2 + c4 * 4);
            float4 bb = *(const float4*)(b1 + c4 * 4);
            v.x = fmaxf(v.x + bb.x, 0.f);
            v.y = fmaxf(v.y + bb.y, 0.f);
            v.z = fmaxf(v.z + bb.z, 0.f);
            v.w = fmaxf(v.w + bb.w, 0.f);
        }
        *(float4*)&xs[r][c4 * 4] = v;
    }
    __syncthreads();

    float acc[4][8];
#pragma unroll
    for (int i = 0; i < 4; i++)
#pragma unroll
        for (int j = 0; j < 8; j++) acc[i][j] = 0.f;

#pragma unroll
    for (int k = 0; k < 64; k++) {
        float a[4], b[8];
#pragma unroll
        for (int i = 0; i < 4; i++) a[i] = xs[ty * 4 + i][k];
#pragma unroll
        for (int j = 0; j < 8; j++) b[j] = ws[k][tx * 8 + j];
#pragma unroll
        for (int i = 0; i < 4; i++)
#pragma unroll
            for (int j = 0; j < 8; j++) acc[i][j] += a[i] * b[j];
    }

#pragma unroll
    for (int i = 0; i < 4; i++) {
        int grow = row0 + ty * 4 + i;
        if (grow < NN) {
            float4 v0 = make_float4(acc[i][0], acc[i][1], acc[i][2], acc[i][3]);
            float4 v1 = make_float4(acc[i][4], acc[i][5], acc[i][6], acc[i][7]);
            *(float4*)(g_h2pre + (size_t)grow * C3 + tx * 8) = v0;
            *(float4*)(g_h2pre + (size_t)grow * C3 + tx * 8 + 4) = v1;
        }
    }
}

// ---------------- mean pool: gsum[f] = sum_n relu(h2agg + b2) ----------------
__global__ void finsum_k(const float* __restrict__ b2) {
    __shared__ float sm[256];
    int f = threadIdx.x & 127;
    int half = threadIdx.x >> 7;
    float bias = b2[f];
    float s = 0.f;
    int n0 = blockIdx.x * 128;
    int n1 = n0 + 128;
    if (n1 > NN) n1 = NN;
    for (int n = n0 + half; n < n1; n += 2)
        s += fmaxf(g_h2agg[(size_t)n * C3 + f] + bias, 0.f);
    sm[threadIdx.x] = s;
    __syncthreads();
    if (threadIdx.x < 128)
        atomicAdd(&g_gsum[f], sm[threadIdx.x] + sm[threadIdx.x + 128]);
}

// ---------------- final FC: out[k] = (gsum/N) . fcW[k] + fcb[k] ----------------
__global__ void fc_k(const float* __restrict__ fcW, const float* __restrict__ fcb,
                     float* __restrict__ out) {
    int k = threadIdx.x >> 5, lane = threadIdx.x & 31;
    float s = 0.f;
    for (int f = lane; f < C3; f += 32) s += g_gsum[f] * fcW[k * C3 + f];
#pragma unroll
    for (int o = 16; o; o >>= 1) s += __shfl_down_sync(0xffffffffu, s, o);
    if (lane == 0) out[k] = s * (1.f / NN) + fcb[k];
}

extern "C" void kernel_launch(void* const* d_in, const int* in_sizes, int n_in,
                              void* d_out, int out_size) {
    const float* x   = (const float*)d_in[0];
    const int*   ei  = (const int*)d_in[1];          // int32! (jax x64 disabled)
    const float* W1  = (const float*)d_in[2];
    const float* b1  = (const float*)d_in[3];
    const float* W2  = (const float*)d_in[4];
    const float* b2  = (const float*)d_in[5];
    const float* fcW = (const float*)d_in[6];
    const float* fcb = (const float*)d_in[7];
    float* out = (float*)d_out;

    deginit_k<<<(NN + 255) / 256, 256>>>();
    degcnt_k<<<(NE + 255) / 256, 256>>>(ei);
    dinv_k<<<(NN + 255) / 256, 256>>>();

    gemm1_k<<<(NN + 63) / 64, 256>>>(x, W1);
    self1_k<<<(NN * 16 + 255) / 256, 256>>>();
    agg1_k<<<NE / 8, 256>>>(ei);          // 1 warp per edge, 8 edges/block

    gemm2_k<<<(NN + 63) / 64, 256>>>(W2, b1);
    self2_k<<<(NN * 32 + 255) / 256, 256>>>();
    agg2_k<<<NE / 8, 256>>>(ei);

    finsum_k<<<(NN + 127) / 128, 256>>>(b2);
    fc_k<<<1, 64>>>(fcW, fcb, out);
}

// round 6
// speedup vs baseline: 1.7070x; 1.7070x over previous
#include <cuda_runtime.h>

#define NN 100000
#define NE 3200000
#define C1 256
#define C2 64
#define C3 128

// Scratch (static device globals — no allocation allowed)
__device__ float g_hs1[(size_t)NN * C2];   // dinv * (x @ W1)
__device__ float g_a1 [(size_t)NN * C2];   // accumulator layer1 (init = hs1)
__device__ float g_rs1[(size_t)NN * C2];   // dinv * relu(dinv*a1 + b1)
__device__ float g_a2 [(size_t)NN * C2];   // accumulator layer2 (init = rs1)
__device__ int   g_deg[NN];
__device__ float g_dinv[NN];
__device__ float g_gsum[C3];

// ---------------- degree / norm ----------------
__global__ void deginit_k() {
    int i = blockIdx.x * blockDim.x + threadIdx.x;
    if (i < NN) g_deg[i] = 1;          // self loop
    if (i < C3) g_gsum[i] = 0.f;
}

__global__ void degcnt_k(const int* __restrict__ ei) {
    int e = blockIdx.x * blockDim.x + threadIdx.x;
    if (e < NE) atomicAdd(&g_deg[ei[NE + e]], 1);
}

__global__ void dinv_k() {
    int i = blockIdx.x * blockDim.x + threadIdx.x;
    if (i < NN) g_dinv[i] = rsqrtf((float)g_deg[i]);
}

// ---------------- GEMM1: hs1 = dinv * (x @ W1); a1 = hs1 ----------------
__global__ void gemm1_k(const float* __restrict__ x, const float* __restrict__ W1) {
    __shared__ float xs[64][68];
    __shared__ float ws[64][68];
    int row0 = blockIdx.x * 64;
    int tid = threadIdx.x;
    int ty = tid >> 4, tx = tid & 15;
    float acc[4][4];
#pragma unroll
    for (int i = 0; i < 4; i++)
#pragma unroll
        for (int j = 0; j < 4; j++) acc[i][j] = 0.f;

    for (int kc = 0; kc < C1; kc += 64) {
#pragma unroll
        for (int i = 0; i < 4; i++) {
            int li = tid + i * 256;            // float4 index 0..1023
            int r = li >> 4, c4 = li & 15;
            int grow = row0 + r;
            float4 v = make_float4(0.f, 0.f, 0.f, 0.f);
            if (grow < NN) v = *(const float4*)(x + (size_t)grow * C1 + kc + c4 * 4);
            *(float4*)&xs[r][c4 * 4] = v;
        }
#pragma unroll
        for (int i = 0; i < 4; i++) {
            int li = tid + i * 256;
            int r = li >> 4, c4 = li & 15;
            *(float4*)&ws[r][c4 * 4] = *(const float4*)(W1 + (size_t)(kc + r) * C2 + c4 * 4);
        }
        __syncthreads();
#pragma unroll
        for (int k = 0; k < 64; k++) {
            float a[4], b[4];
#pragma unroll
            for (int i = 0; i < 4; i++) a[i] = xs[ty * 4 + i][k];
#pragma unroll
            for (int j = 0; j < 4; j++) b[j] = ws[k][tx * 4 + j];
#pragma unroll
            for (int i = 0; i < 4; i++)
#pragma unroll
                for (int j = 0; j < 4; j++) acc[i][j] += a[i] * b[j];
        }
        __syncthreads();
    }
#pragma unroll
    for (int i = 0; i < 4; i++) {
        int grow = row0 + ty * 4 + i;
        if (grow < NN) {
            float dv = g_dinv[grow];
            float4 v = make_float4(acc[i][0] * dv, acc[i][1] * dv,
                                   acc[i][2] * dv, acc[i][3] * dv);
            *(float4*)(g_hs1 + (size_t)grow * C2 + tx * 4) = v;
            *(float4*)(g_a1  + (size_t)grow * C2 + tx * 4) = v;
        }
    }
}

// ---------------- edge scatter: 16 lanes per edge, float4 atomics ----------------
// (globals referenced from device code — passing __device__ symbols as kernel
//  args from host code is UB and was the R3 bug)
__global__ void agg1_k(const int* __restrict__ ei) {
    int t = blockIdx.x * blockDim.x + threadIdx.x;
    int e = t >> 4;
    if (e >= NE) return;
    int lane = t & 15;
    int s = __ldg(ei + e);
    int d = __ldg(ei + NE + e);
    float4 v = *(const float4*)(g_hs1 + (size_t)s * C2 + lane * 4);
    atomicAdd((float4*)(g_a1 + (size_t)d * C2 + lane * 4), v);
}

__global__ void agg2_k(const int* __restrict__ ei) {
    int t = blockIdx.x * blockDim.x + threadIdx.x;
    int e = t >> 4;
    if (e >= NE) return;
    int lane = t & 15;
    int s = __ldg(ei + e);
    int d = __ldg(ei + NE + e);
    float4 v = *(const float4*)(g_rs1 + (size_t)s * C2 + lane * 4);
    atomicAdd((float4*)(g_a2 + (size_t)d * C2 + lane * 4), v);
}

// ---------------- post layer1: rs1 = dinv*relu(dinv*a1 + b1); a2 = rs1 ----------------
__global__ void post1_k(const float* __restrict__ b1) {
    int i = blockIdx.x * blockDim.x + threadIdx.x;   // float4 index
    if (i >= NN * 16) return;
    int node = i >> 4;
    float dv = g_dinv[node];
    float4 bb = *(const float4*)(b1 + (i & 15) * 4);
    float4 v = *((const float4*)g_a1 + i);
    v.x = fmaxf(v.x * dv + bb.x, 0.f) * dv;
    v.y = fmaxf(v.y * dv + bb.y, 0.f) * dv;
    v.z = fmaxf(v.z * dv + bb.z, 0.f) * dv;
    v.w = fmaxf(v.w * dv + bb.w, 0.f) * dv;
    *((float4*)g_rs1 + i) = v;
    *((float4*)g_a2  + i) = v;
}

// --------- GEMM2 + mean fused: gsum += colsum(relu((dinv*a2) @ W2 + b2)) ---------
__global__ void gemm2mean_k(const float* __restrict__ W2, const float* __restrict__ b2) {
    __shared__ float xs[64][64];
    __shared__ float ws[64][128];
    __shared__ float rsm[16][132];
    int row0 = blockIdx.x * 64;
    int tid = threadIdx.x;
    int ty = tid >> 4, tx = tid & 15;

    // load W2 fully: 64x128 floats = 2048 float4, 8 per thread
#pragma unroll
    for (int i = 0; i < 8; i++) {
        int li = tid + i * 256;            // 32 float4 per row
        int r = li >> 5, c4 = li & 31;
        *(float4*)&ws[r][c4 * 4] = *(const float4*)(W2 + (size_t)r * C3 + c4 * 4);
    }
    // load x tile = dinv[row] * a2[row]
#pragma unroll
    for (int i = 0; i < 4; i++) {
        int li = tid + i * 256;            // 16 float4 per row
        int r = li >> 4, c4 = li & 15;
        int grow = row0 + r;
        float4 v = make_float4(0.f, 0.f, 0.f, 0.f);
        if (grow < NN) {
            v = *(const float4*)(g_a2 + (size_t)grow * C2 + c4 * 4);
            float dv = g_dinv[grow];
            v.x *= dv; v.y *= dv; v.z *= dv; v.w *= dv;
        }
        *(float4*)&xs[r][c4 * 4] = v;
    }
    __syncthreads();

    float acc[4][8];
#pragma unroll
    for (int i = 0; i < 4; i++)
#pragma unroll
        for (int j = 0; j < 8; j++) acc[i][j] = 0.f;

#pragma unroll
    for (int k = 0; k < 64; k++) {
        float a[4], b[8];
#pragma unroll
        for (int i = 0; i < 4; i++) a[i] = xs[ty * 4 + i][k];
#pragma unroll
        for (int j = 0; j < 8; j++) b[j] = ws[k][tx * 8 + j];
#pragma unroll
        for (int i = 0; i < 4; i++)
#pragma unroll
            for (int j = 0; j < 8; j++) acc[i][j] += a[i] * b[j];
    }

    // bias + relu + per-thread row reduction (4 rows -> 1)
    float part[8];
#pragma unroll
    for (int j = 0; j < 8; j++) {
        float bias = b2[tx * 8 + j];
        float s = 0.f;
#pragma unroll
        for (int i = 0; i < 4; i++) {
            int grow = row0 + ty * 4 + i;
            if (grow < NN) s += fmaxf(acc[i][j] + bias, 0.f);
        }
        part[j] = s;
    }
#pragma unroll
    for (int j = 0; j < 8; j++) rsm[ty][tx * 8 + j] = part[j];
    __syncthreads();

    // reduce 16 partial rows per column, 128 columns by threads 0..127
    if (tid < C3) {
        float s = 0.f;
#pragma unroll
        for (int r = 0; r < 16; r++) s += rsm[r][tid];
        atomicAdd(&g_gsum[tid], s);
    }
}

// ---------------- final FC: out[k] = (gsum/N) . fcW[k] + fcb[k] ----------------
__global__ void fc_k(const float* __restrict__ fcW, const float* __restrict__ fcb,
                     float* __restrict__ out) {
    int k = threadIdx.x >> 5, lane = threadIdx.x & 31;
    float s = 0.f;
    for (int f = lane; f < C3; f += 32) s += g_gsum[f] * fcW[k * C3 + f];
#pragma unroll
    for (int o = 16; o; o >>= 1) s += __shfl_down_sync(0xffffffffu, s, o);
    if (lane == 0) out[k] = s * (1.f / NN) + fcb[k];
}

extern "C" void kernel_launch(void* const* d_in, const int* in_sizes, int n_in,
                              void* d_out, int out_size) {
    const float* x   = (const float*)d_in[0];
    const int*   ei  = (const int*)d_in[1];          // int32 (jax x64 disabled)
    const float* W1  = (const float*)d_in[2];
    const float* b1  = (const float*)d_in[3];
    const float* W2  = (const float*)d_in[4];
    const float* b2  = (const float*)d_in[5];
    const float* fcW = (const float*)d_in[6];
    const float* fcb = (const float*)d_in[7];
    float* out = (float*)d_out;

    deginit_k<<<(NN + 255) / 256, 256>>>();
    degcnt_k<<<(NE + 255) / 256, 256>>>(ei);
    dinv_k<<<(NN + 255) / 256, 256>>>();

    gemm1_k<<<(NN + 63) / 64, 256>>>(x, W1);
    agg1_k<<<NE / 16, 256>>>(ei);     // 16 lanes/edge, 16 edges/block

    post1_k<<<(NN * 16 + 255) / 256, 256>>>(b1);
    agg2_k<<<NE / 16, 256>>>(ei);

    gemm2mean_k<<<(NN + 63) / 64, 256>>>(W2, b2);
    fc_k<<<1, 64>>>(fcW, fcb, out);
}

// round 7
// speedup vs baseline: 2.6458x; 1.5499x over previous
#include <cuda_runtime.h>

#define NN 100000
#define NE 3200000
#define C1 256
#define C2 64
#define C3 128
#define NBLK ((NN + 255) / 256)   // 391

// Scratch (static device globals — no allocation allowed)
__device__ float g_hs1[(size_t)NN * C2];   // dinv * (x @ W1)
__device__ float g_rs1[(size_t)NN * C2];   // dinv * relu(dinv*agg1 + b1)
__device__ float g_a2 [(size_t)NN * C2];   // layer2 aggregate (pre-dinv)
__device__ int   g_deg[NN];
__device__ float g_dinv[NN];
__device__ float g_gsum[C3];
// CSR of in-edges
__device__ int   g_off[NN + 1];
__device__ int   g_cur[NN];
__device__ int   g_csrc[NE];
__device__ int   g_bsum[512];
__device__ int   g_bpre[512];

// ---------------- degree / norm ----------------
__global__ void deginit_k() {
    int i = blockIdx.x * blockDim.x + threadIdx.x;
    if (i < NN) g_deg[i] = 1;          // self loop
    if (i < C3) g_gsum[i] = 0.f;
}

__global__ void degcnt_k(const int* __restrict__ ei) {
    int e = blockIdx.x * blockDim.x + threadIdx.x;
    if (e < NE) atomicAdd(&g_deg[ei[NE + e]], 1);
}

__global__ void dinv_k() {
    int i = blockIdx.x * blockDim.x + threadIdx.x;
    if (i < NN) g_dinv[i] = rsqrtf((float)g_deg[i]);
}

// ---------------- CSR build: scan of (deg-1), then cursor fill ----------------
__global__ void scanA_k() {      // per-block sums
    __shared__ int sm[256];
    int i = blockIdx.x * 256 + threadIdx.x;
    sm[threadIdx.x] = (i < NN) ? (g_deg[i] - 1) : 0;
    __syncthreads();
    for (int o = 128; o; o >>= 1) {
        if (threadIdx.x < o) sm[threadIdx.x] += sm[threadIdx.x + o];
        __syncthreads();
    }
    if (threadIdx.x == 0) g_bsum[blockIdx.x] = sm[0];
}

__global__ void scanB_k() {      // exclusive scan of block sums (1 block, 512 thr)
    __shared__ int sm[512];
    int t = threadIdx.x;
    int v = (t < NBLK) ? g_bsum[t] : 0;
    sm[t] = v;
    __syncthreads();
    for (int o = 1; o < 512; o <<= 1) {
        int add = (t >= o) ? sm[t - o] : 0;
        __syncthreads();
        sm[t] += add;
        __syncthreads();
    }
    if (t < NBLK) g_bpre[t] = sm[t] - v;
}

__global__ void scanC_k() {      // intra-block exclusive scan + base -> offsets
    __shared__ int sm[256];
    int t = threadIdx.x;
    int i = blockIdx.x * 256 + t;
    int v = (i < NN) ? (g_deg[i] - 1) : 0;
    sm[t] = v;
    __syncthreads();
    for (int o = 1; o < 256; o <<= 1) {
        int add = (t >= o) ? sm[t - o] : 0;
        __syncthreads();
        sm[t] += add;
        __syncthreads();
    }
    if (i < NN) {
        int off = g_bpre[blockIdx.x] + sm[t] - v;
        g_off[i] = off;
        g_cur[i] = off;
    }
    if (i == 0) g_off[NN] = NE;
}

__global__ void fill_k(const int* __restrict__ ei) {
    int e = blockIdx.x * blockDim.x + threadIdx.x;
    if (e >= NE) return;
    int s = ei[e];
    int d = ei[NE + e];
    int pos = atomicAdd(&g_cur[d], 1);
    g_csrc[pos] = s;
}

// ---------------- GEMM1: hs1 = dinv * (x @ W1) ----------------
__global__ void gemm1_k(const float* __restrict__ x, const float* __restrict__ W1) {
    __shared__ float xs[64][68];
    __shared__ float ws[64][68];
    int row0 = blockIdx.x * 64;
    int tid = threadIdx.x;
    int ty = tid >> 4, tx = tid & 15;
    float acc[4][4];
#pragma unroll
    for (int i = 0; i < 4; i++)
#pragma unroll
        for (int j = 0; j < 4; j++) acc[i][j] = 0.f;

    for (int kc = 0; kc < C1; kc += 64) {
#pragma unroll
        for (int i = 0; i < 4; i++) {
            int li = tid + i * 256;            // float4 index 0..1023
            int r = li >> 4, c4 = li & 15;
            int grow = row0 + r;
            float4 v = make_float4(0.f, 0.f, 0.f, 0.f);
            if (grow < NN) v = *(const float4*)(x + (size_t)grow * C1 + kc + c4 * 4);
            *(float4*)&xs[r][c4 * 4] = v;
        }
#pragma unroll
        for (int i = 0; i < 4; i++) {
            int li = tid + i * 256;
            int r = li >> 4, c4 = li & 15;
            *(float4*)&ws[r][c4 * 4] = *(const float4*)(W1 + (size_t)(kc + r) * C2 + c4 * 4);
        }
        __syncthreads();
#pragma unroll
        for (int k = 0; k < 64; k++) {
            float a[4], b[4];
#pragma unroll
            for (int i = 0; i < 4; i++) a[i] = xs[ty * 4 + i][k];
#pragma unroll
            for (int j = 0; j < 4; j++) b[j] = ws[k][tx * 4 + j];
#pragma unroll
            for (int i = 0; i < 4; i++)
#pragma unroll
                for (int j = 0; j < 4; j++) acc[i][j] += a[i] * b[j];
        }
        __syncthreads();
    }
#pragma unroll
    for (int i = 0; i < 4; i++) {
        int grow = row0 + ty * 4 + i;
        if (grow < NN) {
            float dv = g_dinv[grow];
            float4 v = make_float4(acc[i][0] * dv, acc[i][1] * dv,
                                   acc[i][2] * dv, acc[i][3] * dv);
            *(float4*)(g_hs1 + (size_t)grow * C2 + tx * 4) = v;
        }
    }
}

// ------------- pull aggregation layer1: one warp per node, reg accumulate -------------
// rs1[d] = dinv_d * relu(dinv_d * (hs1[d] + sum_in hs1[s]) + b1)
__global__ void pull1_k(const float* __restrict__ b1) {
    int w = (blockIdx.x * blockDim.x + threadIdx.x) >> 5;
    if (w >= NN) return;
    int lane = threadIdx.x & 31;
    int beg = g_off[w], end = g_off[w + 1];
    float2 acc = *((const float2*)(g_hs1 + w * C2) + lane);   // self loop
    int i = beg;
    while (i < end) {
        int n = end - i; if (n > 32) n = 32;
        int idx = 0;
        if (lane < n) idx = __ldg(g_csrc + i + lane);
#pragma unroll 4
        for (int j = 0; j < n; j++) {
            int s = __shfl_sync(0xffffffffu, idx, j);
            float2 v = *((const float2*)(g_hs1 + s * C2) + lane);
            acc.x += v.x; acc.y += v.y;
        }
        i += n;
    }
    float dv = g_dinv[w];
    float2 bb = *((const float2*)b1 + lane);
    acc.x = fmaxf(acc.x * dv + bb.x, 0.f) * dv;
    acc.y = fmaxf(acc.y * dv + bb.y, 0.f) * dv;
    *((float2*)(g_rs1 + w * C2) + lane) = acc;
}

// ------------- pull aggregation layer2: a2[d] = rs1[d] + sum_in rs1[s] -------------
__global__ void pull2_k() {
    int w = (blockIdx.x * blockDim.x + threadIdx.x) >> 5;
    if (w >= NN) return;
    int lane = threadIdx.x & 31;
    int beg = g_off[w], end = g_off[w + 1];
    float2 acc = *((const float2*)(g_rs1 + w * C2) + lane);   // self loop
    int i = beg;
    while (i < end) {
        int n = end - i; if (n > 32) n = 32;
        int idx = 0;
        if (lane < n) idx = __ldg(g_csrc + i + lane);
#pragma unroll 4
        for (int j = 0; j < n; j++) {
            int s = __shfl_sync(0xffffffffu, idx, j);
            float2 v = *((const float2*)(g_rs1 + s * C2) + lane);
            acc.x += v.x; acc.y += v.y;
        }
        i += n;
    }
    *((float2*)(g_a2 + w * C2) + lane) = acc;
}

// --------- GEMM2 + mean fused: gsum += colsum(relu((dinv*a2) @ W2 + b2)) ---------
__global__ void gemm2mean_k(const float* __restrict__ W2, const float* __restrict__ b2) {
    __shared__ float xs[64][64];
    __shared__ float ws[64][128];
    __shared__ float rsm[16][132];
    int row0 = blockIdx.x * 64;
    int tid = threadIdx.x;
    int ty = tid >> 4, tx = tid & 15;

#pragma unroll
    for (int i = 0; i < 8; i++) {
        int li = tid + i * 256;            // 32 float4 per row
        int r = li >> 5, c4 = li & 31;
        *(float4*)&ws[r][c4 * 4] = *(const float4*)(W2 + (size_t)r * C3 + c4 * 4);
    }
#pragma unroll
    for (int i = 0; i < 4; i++) {
        int li = tid + i * 256;            // 16 float4 per row
        int r = li >> 4, c4 = li & 15;
        int grow = row0 + r;
        float4 v = make_float4(0.f, 0.f, 0.f, 0.f);
        if (grow < NN) {
            v = *(const float4*)(g_a2 + (size_t)grow * C2 + c4 * 4);
            float dv = g_dinv[grow];
            v.x *= dv; v.y *= dv; v.z *= dv; v.w *= dv;
        }
        *(float4*)&xs[r][c4 * 4] = v;
    }
    __syncthreads();

    float acc[4][8];
#pragma unroll
    for (int i = 0; i < 4; i++)
#pragma unroll
        for (int j = 0; j < 8; j++) acc[i][j] = 0.f;

#pragma unroll
    for (int k = 0; k < 64; k++) {
        float a[4], b[8];
#pragma unroll
        for (int i = 0; i < 4; i++) a[i] = xs[ty * 4 + i][k];
#pragma unroll
        for (int j = 0; j < 8; j++) b[j] = ws[k][tx * 8 + j];
#pragma unroll
        for (int i = 0; i < 4; i++)
#pragma unroll
            for (int j = 0; j < 8; j++) acc[i][j] += a[i] * b[j];
    }

    float part[8];
#pragma unroll
    for (int j = 0; j < 8; j++) {
        float bias = b2[tx * 8 + j];
        float s = 0.f;
#pragma unroll
        for (int i = 0; i < 4; i++) {
            int grow = row0 + ty * 4 + i;
            if (grow < NN) s += fmaxf(acc[i][j] + bias, 0.f);
        }
        part[j] = s;
    }
#pragma unroll
    for (int j = 0; j < 8; j++) rsm[ty][tx * 8 + j] = part[j];
    __syncthreads();

    if (tid < C3) {
        float s = 0.f;
#pragma unroll
        for (int r = 0; r < 16; r++) s += rsm[r][tid];
        atomicAdd(&g_gsum[tid], s);
    }
}

// ---------------- final FC: out[k] = (gsum/N) . fcW[k] + fcb[k] ----------------
__global__ void fc_k(const float* __restrict__ fcW, const float* __restrict__ fcb,
                     float* __restrict__ out) {
    int k = threadIdx.x >> 5, lane = threadIdx.x & 31;
    float s = 0.f;
    for (int f = lane; f < C3; f += 32) s += g_gsum[f] * fcW[k * C3 + f];
#pragma unroll
    for (int o = 16; o; o >>= 1) s += __shfl_down_sync(0xffffffffu, s, o);
    if (lane == 0) out[k] = s * (1.f / NN) + fcb[k];
}

extern "C" void kernel_launch(void* const* d_in, const int* in_sizes, int n_in,
                              void* d_out, int out_size) {
    const float* x   = (const float*)d_in[0];
    const int*   ei  = (const int*)d_in[1];          // int32 (jax x64 disabled)
    const float* W1  = (const float*)d_in[2];
    const float* b1  = (const float*)d_in[3];
    const float* W2  = (const float*)d_in[4];
    const float* b2  = (const float*)d_in[5];
    const float* fcW = (const float*)d_in[6];
    const float* fcb = (const float*)d_in[7];
    float* out = (float*)d_out;

    deginit_k<<<NBLK, 256>>>();
    degcnt_k<<<(NE + 255) / 256, 256>>>(ei);
    dinv_k<<<NBLK, 256>>>();

    // CSR build (reused by both layers)
    scanA_k<<<NBLK, 256>>>();
    scanB_k<<<1, 512>>>();
    scanC_k<<<NBLK, 256>>>();
    fill_k<<<(NE + 255) / 256, 256>>>(ei);

    gemm1_k<<<(NN + 63) / 64, 256>>>(x, W1);
    pull1_k<<<(NN * 32 + 255) / 256, 256>>>(b1);    // warp per node
    pull2_k<<<(NN * 32 + 255) / 256, 256>>>();

    gemm2mean_k<<<(NN + 63) / 64, 256>>>(W2, b2);
    fc_k<<<1, 64>>>(fcW, fcb, out);
}